// round 6
// baseline (speedup 1.0000x reference)
#include <cuda_runtime.h>
#include <math.h>

// N = 100000 nodes, E = 3200000 edges.
// Accumulators split by finalize-ownership (no cross-thread read/zero race):
//   g_q[i]  = {sumQ0, sumQ1, sumQ2, sumQ3}  -- owned by q-path thread i
//   g_zl[i] = {Z, sumL}                     -- owned by levels-path thread i
// Zero-invariant: zeroed at module load; each finalize thread re-zeroes
// exactly the words it read, so graph replays start from zeros.
#define MAXN 131072
__device__ float4 g_q[MAXN];
__device__ float2 g_zl[MAXN];

#define TEMP 10.0f

// ---------------------------------------------------------------------------
// Edge scatter, 2 edges per thread.
//   accu_q = qmul(rel_q, q_src); ex = exp(TEMP*w*l_src)
//   v4 RED {ex*accu_q} -> g_q[dst];  v2 RED {ex, ex*l} -> g_zl[dst]
// Logits bounded in [0,10) -> stable-softmax max subtraction cancels, omitted.
// ---------------------------------------------------------------------------
__device__ __forceinline__ void edge_body(int s, int d, float4 a, float w,
                                          const float* __restrict__ node_levels,
                                          const float4* __restrict__ node_q) {
    float4 b = __ldg(&node_q[s]);
    float l  = __ldg(&node_levels[s]);

    float aw = a.x, ax = a.y, ay = a.z, az = a.w;
    float bw = b.x, bx = b.y, by = b.z, bz = b.w;
    float cw = aw * bw - ax * bx - ay * by - az * bz;
    float cx = aw * bx + ax * bw + ay * bz - az * by;
    float cy = aw * by - ax * bz + ay * bw + az * bx;
    float cz = aw * bz + ax * by - ay * bx + az * bw;

    float ex = __expf(TEMP * w * l);

    asm volatile("red.global.add.v4.f32 [%0], {%1, %2, %3, %4};"
                 :: "l"(&g_q[d]), "f"(ex * cw), "f"(ex * cx),
                    "f"(ex * cy), "f"(ex * cz)
                 : "memory");
    asm volatile("red.global.add.v2.f32 [%0], {%1, %2};"
                 :: "l"(&g_zl[d]), "f"(ex), "f"(ex * l)
                 : "memory");
}

__global__ void __launch_bounds__(256) edge_kernel(
    const float* __restrict__ node_levels,
    const float4* __restrict__ node_q,
    const float4* __restrict__ edge_rel_q,
    const float* __restrict__ edge_w,
    const int* __restrict__ src,
    const int* __restrict__ dst,
    int E) {
    int t = blockIdx.x * blockDim.x + threadIdx.x;
    int e = 2 * t;
    if (e >= E) return;

    if (e + 1 < E) {
        int2   s2 = __ldg(&((const int2*)src)[t]);
        int2   d2 = __ldg(&((const int2*)dst)[t]);
        float2 w2 = __ldg(&((const float2*)edge_w)[t]);
        float4 a0 = __ldg(&edge_rel_q[e]);
        float4 a1 = __ldg(&edge_rel_q[e + 1]);
        edge_body(s2.x, d2.x, a0, w2.x, node_levels, node_q);
        edge_body(s2.y, d2.y, a1, w2.y, node_levels, node_q);
    } else {
        edge_body(__ldg(&src[e]), __ldg(&dst[e]), __ldg(&edge_rel_q[e]),
                  __ldg(&edge_w[e]), node_levels, node_q);
    }
}

// ---------------------------------------------------------------------------
// Finalize with 2N threads for latency hiding. Disjoint ownership:
//   threads [0,N):  read+zero g_q[i];  out_q = normalize(sum_q + es*q)
//                   (Z cancels inside normalize)
//   threads [N,2N): read+zero g_zl[i]; out_levels = (sumL + es*l)/(Z + es)
// Output layout: out[0..4N) = out_q row-major, out[4N..5N) = out_levels.
// ---------------------------------------------------------------------------
__global__ void __launch_bounds__(256) final_kernel(
    const float* __restrict__ node_levels,
    const float4* __restrict__ node_q,
    float* __restrict__ out, int N) {
    int t = blockIdx.x * blockDim.x + threadIdx.x;

    if (t < N) {
        int i = t;
        float4 acc = g_q[i];
        g_q[i] = make_float4(0.f, 0.f, 0.f, 0.f);   // restore zero-invariant

        float l  = __ldg(&node_levels[i]);
        float4 q = __ldg(&node_q[i]);
        float es = __expf(TEMP * l);

        float q0 = acc.x + es * q.x;
        float q1 = acc.y + es * q.y;
        float q2 = acc.z + es * q.z;
        float q3 = acc.w + es * q.w;

        float n2 = q0 * q0 + q1 * q1 + q2 * q2 + q3 * q3;
        float inv = rsqrtf(fmaxf(n2, 1e-24f));
        ((float4*)out)[i] = make_float4(q0 * inv, q1 * inv, q2 * inv, q3 * inv);
    } else if (t < 2 * N) {
        int i = t - N;
        float2 zl = g_zl[i];
        g_zl[i] = make_float2(0.f, 0.f);            // restore zero-invariant

        float l  = __ldg(&node_levels[i]);
        float es = __expf(TEMP * l);
        float Z    = zl.x + es;
        float sumL = zl.y + es * l;
        out[4 * N + i] = __fdividef(sumL, Z);
    }
}

extern "C" void kernel_launch(void* const* d_in, const int* in_sizes, int n_in,
                              void* d_out, int out_size) {
    const float*  node_levels = (const float*)d_in[0];
    const float4* node_q      = (const float4*)d_in[1];
    const float4* edge_rel_q  = (const float4*)d_in[2];
    const float*  edge_w      = (const float*)d_in[3];
    const int*    src         = (const int*)d_in[4];
    const int*    dst         = (const int*)d_in[5];

    int N = in_sizes[0];
    int E = in_sizes[3];

    float* out = (float*)d_out;

    const int T = 256;
    int edge_threads = (E + 1) / 2;
    edge_kernel<<<(edge_threads + T - 1) / T, T>>>(node_levels, node_q,
                                                   edge_rel_q, edge_w,
                                                   src, dst, E);
    final_kernel<<<(2 * N + T - 1) / T, T>>>(node_levels, node_q, out, N);
}

// round 8
// speedup vs baseline: 1.1470x; 1.1470x over previous
#include <cuda_runtime.h>
#include <math.h>

// N = 100000 nodes, E = 3200000 edges.
// g_packed[i] = {copysign(l_i, qw_i), qx_i, qy_i, qz_i}  (one 16B node record;
//   qw reconstructed from unit norm, sign carried on l which is >= 0)
// g_q[i]  = {sumQ0..3}   -- edge-weighted quaternion accumulator
// g_zl[i] = {Z, sumL}
// Zero-invariant: g_q/g_zl zeroed at module load; finalize thread i reads and
// re-zeroes exactly its own entries, so graph replays start from zeros.
#define MAXN 131072
__device__ float4 g_packed[MAXN];
__device__ float4 g_q[MAXN];
__device__ float2 g_zl[MAXN];

#define TEMP 10.0f

// ---------------------------------------------------------------------------
// Prep: build packed node records (fully overwritten every call).
// node_q rows are (w,x,y,z): .x = scalar part.
// ---------------------------------------------------------------------------
__global__ void __launch_bounds__(256) prep_kernel(
    const float* __restrict__ node_levels,
    const float4* __restrict__ node_q,
    int N) {
    int i = blockIdx.x * blockDim.x + threadIdx.x;
    if (i >= N) return;
    float l  = node_levels[i];
    float4 q = node_q[i];
    g_packed[i] = make_float4(copysignf(l, q.x), q.y, q.z, q.w);
}

__device__ __forceinline__ void unpack_node(float4 p, float& l,
                                            float& bw, float& bx,
                                            float& by, float& bz) {
    l  = fabsf(p.x);
    bx = p.y; by = p.z; bz = p.w;
    bw = copysignf(sqrtf(fmaxf(1.0f - (bx * bx + by * by + bz * bz), 0.0f)),
                   p.x);
}

// ---------------------------------------------------------------------------
// Edge scatter, 2 edges per thread: ONE random 16B gather per edge.
//   accu_q = qmul(rel_q, q_src); ex = exp(TEMP*w*l_src)
//   v4 RED {ex*accu_q} -> g_q[dst];  v2 RED {ex, ex*l} -> g_zl[dst]
// Logits bounded in [0,10) -> stable-softmax max subtraction cancels, omitted.
// ---------------------------------------------------------------------------
__device__ __forceinline__ void edge_body(int s, int d, float4 a, float w) {
    float4 p = __ldg(&g_packed[s]);
    float l, bw, bx, by, bz;
    unpack_node(p, l, bw, bx, by, bz);

    float aw = a.x, ax = a.y, ay = a.z, az = a.w;
    float cw = aw * bw - ax * bx - ay * by - az * bz;
    float cx = aw * bx + ax * bw + ay * bz - az * by;
    float cy = aw * by - ax * bz + ay * bw + az * bx;
    float cz = aw * bz + ax * by - ay * bx + az * bw;

    float ex = __expf(TEMP * w * l);

    asm volatile("red.global.add.v4.f32 [%0], {%1, %2, %3, %4};"
                 :: "l"(&g_q[d]), "f"(ex * cw), "f"(ex * cx),
                    "f"(ex * cy), "f"(ex * cz)
                 : "memory");
    asm volatile("red.global.add.v2.f32 [%0], {%1, %2};"
                 :: "l"(&g_zl[d]), "f"(ex), "f"(ex * l)
                 : "memory");
}

__global__ void __launch_bounds__(256) edge_kernel(
    const float4* __restrict__ edge_rel_q,
    const float* __restrict__ edge_w,
    const int* __restrict__ src,
    const int* __restrict__ dst,
    int E) {
    int t = blockIdx.x * blockDim.x + threadIdx.x;
    int e = 2 * t;
    if (e >= E) return;

    if (e + 1 < E) {
        int2   s2 = __ldg(&((const int2*)src)[t]);
        int2   d2 = __ldg(&((const int2*)dst)[t]);
        float2 w2 = __ldg(&((const float2*)edge_w)[t]);
        float4 a0 = __ldg(&edge_rel_q[e]);
        float4 a1 = __ldg(&edge_rel_q[e + 1]);
        edge_body(s2.x, d2.x, a0, w2.x);
        edge_body(s2.y, d2.y, a1, w2.y);
    } else {
        edge_body(__ldg(&src[e]), __ldg(&dst[e]), __ldg(&edge_rel_q[e]),
                  __ldg(&edge_w[e]));
    }
}

// ---------------------------------------------------------------------------
// Finalize: one thread per node (R6 showed the 2N split is slower).
//   out_q = normalize(sum_q + es*q)   (Z cancels inside normalize)
//   out_levels = (sumL + es*l)/(Z + es)
// Reads g_q, g_zl, g_packed; re-zeroes g_q/g_zl (sole owner -> no race).
// Output layout: out[0..4N) = out_q row-major, out[4N..5N) = out_levels.
// ---------------------------------------------------------------------------
__global__ void __launch_bounds__(256) final_kernel(float* __restrict__ out,
                                                   int N) {
    int i = blockIdx.x * blockDim.x + threadIdx.x;
    if (i >= N) return;

    float4 acc = g_q[i];
    float2 zl  = g_zl[i];
    g_q[i]  = make_float4(0.f, 0.f, 0.f, 0.f);   // restore zero-invariant
    g_zl[i] = make_float2(0.f, 0.f);

    float4 p = g_packed[i];
    float l, bw, bx, by, bz;
    unpack_node(p, l, bw, bx, by, bz);
    float es = __expf(TEMP * l);

    float q0 = acc.x + es * bw;
    float q1 = acc.y + es * bx;
    float q2 = acc.z + es * by;
    float q3 = acc.w + es * bz;

    float n2 = q0 * q0 + q1 * q1 + q2 * q2 + q3 * q3;
    float inv = rsqrtf(fmaxf(n2, 1e-24f));
    ((float4*)out)[i] = make_float4(q0 * inv, q1 * inv, q2 * inv, q3 * inv);

    float Z    = zl.x + es;
    float sumL = zl.y + es * l;
    out[4 * N + i] = __fdividef(sumL, Z);
}

extern "C" void kernel_launch(void* const* d_in, const int* in_sizes, int n_in,
                              void* d_out, int out_size) {
    const float*  node_levels = (const float*)d_in[0];
    const float4* node_q      = (const float4*)d_in[1];
    const float4* edge_rel_q  = (const float4*)d_in[2];
    const float*  edge_w      = (const float*)d_in[3];
    const int*    src         = (const int*)d_in[4];
    const int*    dst         = (const int*)d_in[5];

    int N = in_sizes[0];
    int E = in_sizes[3];

    float* out = (float*)d_out;

    const int T = 256;
    prep_kernel<<<(N + T - 1) / T, T>>>(node_levels, node_q, N);
    int edge_threads = (E + 1) / 2;
    edge_kernel<<<(edge_threads + T - 1) / T, T>>>(edge_rel_q, edge_w,
                                                   src, dst, E);
    final_kernel<<<(N + T - 1) / T, T>>>(out, N);
}

// round 11
// speedup vs baseline: 1.2076x; 1.0529x over previous
#include <cuda_runtime.h>
#include <math.h>

// N = 100000 nodes, E = 3200000 edges.
// g_packed[i] = {copysign(l_i, qw_i), qx, qy, qz}  (16B fp32 node record;
//   l >= 0 so its sign bit carries qw's sign; qw reconstructed from the
//   unit-norm invariant -> full fp32 precision, proven rel_err ~5e-6).
// g_q[i]  = {sumQ0..3}, g_zl[i] = {Z, sumL}: initialized by prep with the
//   exact self term (overwrite), accumulated by edge REDs, read-only in
//   finalize. No zero-invariant -> robust across graph replays.
#define MAXN 131072
__device__ float4 g_packed[MAXN];
__device__ float4 g_q[MAXN];
__device__ float2 g_zl[MAXN];

#define TEMP 10.0f

// ---------------------------------------------------------------------------
// Prep: per node, write packed record AND initialize accumulators with the
// exact self term (es = exp(TEMP*l)).  node_q rows are (w,x,y,z).
// ---------------------------------------------------------------------------
__global__ void __launch_bounds__(256) prep_kernel(
    const float* __restrict__ node_levels,
    const float4* __restrict__ node_q,
    int N) {
    int i = blockIdx.x * blockDim.x + threadIdx.x;
    if (i >= N) return;
    float l  = node_levels[i];
    float4 q = node_q[i];
    float es = __expf(TEMP * l);

    g_q[i]  = make_float4(es * q.x, es * q.y, es * q.z, es * q.w);
    g_zl[i] = make_float2(es, es * l);
    g_packed[i] = make_float4(copysignf(l, q.x), q.y, q.z, q.w);
}

// ---------------------------------------------------------------------------
// Edge scatter, 2 edges per thread. ONE random 16B gather per edge.
//   accu_q = qmul(rel_q, q_src); ex = exp(TEMP*w*l_src)
//   v4 RED {ex*accu_q} -> g_q[dst];  v2 RED {ex, ex*l} -> g_zl[dst]
// Logits bounded in [0,10) -> stable-softmax max subtraction cancels, omitted.
// ---------------------------------------------------------------------------
__device__ __forceinline__ void edge_body(int s, int d, float4 a, float w) {
    float4 p = __ldg(&g_packed[s]);
    float l  = fabsf(p.x);
    float bx = p.y, by = p.z, bz = p.w;
    float t  = 1.0f - (bx * bx + by * by + bz * bz);
    float bw = copysignf(sqrtf(fmaxf(t, 0.0f)), p.x);

    float aw = a.x, ax = a.y, ay = a.z, az = a.w;
    float cw = aw * bw - ax * bx - ay * by - az * bz;
    float cx = aw * bx + ax * bw + ay * bz - az * by;
    float cy = aw * by - ax * bz + ay * bw + az * bx;
    float cz = aw * bz + ax * by - ay * bx + az * bw;

    float ex = __expf(TEMP * w * l);

    asm volatile("red.global.add.v4.f32 [%0], {%1, %2, %3, %4};"
                 :: "l"(&g_q[d]), "f"(ex * cw), "f"(ex * cx),
                    "f"(ex * cy), "f"(ex * cz)
                 : "memory");
    asm volatile("red.global.add.v2.f32 [%0], {%1, %2};"
                 :: "l"(&g_zl[d]), "f"(ex), "f"(ex * l)
                 : "memory");
}

__global__ void __launch_bounds__(256) edge_kernel(
    const float4* __restrict__ edge_rel_q,
    const float* __restrict__ edge_w,
    const int* __restrict__ src,
    const int* __restrict__ dst,
    int E) {
    int t = blockIdx.x * blockDim.x + threadIdx.x;
    int e = 2 * t;
    if (e >= E) return;

    if (e + 1 < E) {
        int2   s2 = __ldg(&((const int2*)src)[t]);
        int2   d2 = __ldg(&((const int2*)dst)[t]);
        float2 w2 = __ldg(&((const float2*)edge_w)[t]);
        float4 a0 = __ldg(&edge_rel_q[e]);
        float4 a1 = __ldg(&edge_rel_q[e + 1]);
        edge_body(s2.x, d2.x, a0, w2.x);
        edge_body(s2.y, d2.y, a1, w2.y);
    } else {
        edge_body(__ldg(&src[e]), __ldg(&dst[e]), __ldg(&edge_rel_q[e]),
                  __ldg(&edge_w[e]));
    }
}

// ---------------------------------------------------------------------------
// Finalize: read-only on accumulators (self term already inside).
//   out_q = normalize(sum_q)            (Z cancels inside normalize)
//   out_levels = sumL / Z
// Output layout: out[0..4N) = out_q row-major, out[4N..5N) = out_levels.
// ---------------------------------------------------------------------------
__global__ void __launch_bounds__(256) final_kernel(float* __restrict__ out,
                                                   int N) {
    int i = blockIdx.x * blockDim.x + threadIdx.x;
    if (i >= N) return;

    float4 acc = g_q[i];
    float2 zl  = g_zl[i];

    float n2 = acc.x * acc.x + acc.y * acc.y + acc.z * acc.z + acc.w * acc.w;
    float inv = rsqrtf(fmaxf(n2, 1e-24f));
    ((float4*)out)[i] = make_float4(acc.x * inv, acc.y * inv,
                                    acc.z * inv, acc.w * inv);
    out[4 * N + i] = __fdividef(zl.y, zl.x);
}

extern "C" void kernel_launch(void* const* d_in, const int* in_sizes, int n_in,
                              void* d_out, int out_size) {
    const float*  node_levels = (const float*)d_in[0];
    const float4* node_q      = (const float4*)d_in[1];
    const float4* edge_rel_q  = (const float4*)d_in[2];
    const float*  edge_w      = (const float*)d_in[3];
    const int*    src         = (const int*)d_in[4];
    const int*    dst         = (const int*)d_in[5];

    int N = in_sizes[0];
    int E = in_sizes[3];

    float* out = (float*)d_out;

    const int T = 256;
    prep_kernel<<<(N + T - 1) / T, T>>>(node_levels, node_q, N);
    int edge_threads = (E + 1) / 2;
    edge_kernel<<<(edge_threads + T - 1) / T, T>>>(edge_rel_q, edge_w,
                                                   src, dst, E);
    final_kernel<<<(N + T - 1) / T, T>>>(out, N);
}